// round 1
// baseline (speedup 1.0000x reference)
#include <cuda_runtime.h>

#define BB 64
#define SS 1024
#define DD 16

// Scratch (allocation-free rule: __device__ globals)
__device__ float4 g_kv[BB * SS];   // (k0, k1, v0, v1) per (b,t)
__device__ float2 g_q[BB * SS];    // q pre-scaled by 0.25 * log2(e)

__device__ __forceinline__ float ex2_approx(float x) {
    float y;
    asm("ex2.approx.f32 %0, %1;" : "=f"(y) : "f"(x));
    return y;
}

// ---------------------------------------------------------------------------
// Kernel 1: QKV projection.  One thread per (b,s) token.
// ---------------------------------------------------------------------------
__global__ void qkv_kernel(const float* __restrict__ x,
                           const float* __restrict__ Wq, const float* __restrict__ bq,
                           const float* __restrict__ Wk, const float* __restrict__ bk,
                           const float* __restrict__ Wv, const float* __restrict__ bv)
{
    __shared__ float sw[102];  // Wq[32] Wk[32] Wv[32] bq[2] bk[2] bv[2]
    int tid = threadIdx.x;
    if (tid < 32)        sw[tid]       = Wq[tid];
    else if (tid < 64)   sw[tid]       = Wk[tid - 32];
    else if (tid < 96)   sw[tid]       = Wv[tid - 64];
    else if (tid < 98)   sw[tid]       = bq[tid - 96];
    else if (tid < 100)  sw[tid]       = bk[tid - 98];
    else if (tid < 102)  sw[tid]       = bv[tid - 100];
    __syncthreads();

    int idx = blockIdx.x * blockDim.x + tid;   // b*S + s
    const float4* xp = reinterpret_cast<const float4*>(x + idx * DD);
    float xv[16];
    #pragma unroll
    for (int c = 0; c < 4; c++) {
        float4 v = xp[c];
        xv[4*c+0] = v.x; xv[4*c+1] = v.y; xv[4*c+2] = v.z; xv[4*c+3] = v.w;
    }

    float q0 = sw[96], q1 = sw[97];
    float k0 = sw[98], k1 = sw[99];
    float v0 = sw[100], v1 = sw[101];
    #pragma unroll
    for (int i = 0; i < 16; i++) {
        float xi = xv[i];
        q0 = fmaf(xi, sw[i*2+0],      q0);
        q1 = fmaf(xi, sw[i*2+1],      q1);
        k0 = fmaf(xi, sw[32+i*2+0],   k0);
        k1 = fmaf(xi, sw[32+i*2+1],   k1);
        v0 = fmaf(xi, sw[64+i*2+0],   v0);
        v1 = fmaf(xi, sw[64+i*2+1],   v1);
    }

    // Pre-fold softmax scale (1/sqrt(16) = 0.25) and log2(e) into Q so the
    // attention inner loop needs only: dot -> ex2.approx.
    const float SC = 0.25f * 1.4426950408889634f;
    g_q[idx]  = make_float2(q0 * SC, q1 * SC);
    g_kv[idx] = make_float4(k0, k1, v0, v1);
}

// ---------------------------------------------------------------------------
// 16x16 dense matmul from SMEM weights (row-major W[i][j] = W[i*16+j]).
// ---------------------------------------------------------------------------
__device__ __forceinline__ void mm16(const float* __restrict__ in,
                                     const float* __restrict__ Ws,
                                     const float* __restrict__ bs,
                                     float* __restrict__ outr)
{
    float acc[16];
    #pragma unroll
    for (int j = 0; j < 16; j++) acc[j] = bs[j];
    #pragma unroll
    for (int i = 0; i < 16; i++) {
        float hv = in[i];
        const float4* wr = reinterpret_cast<const float4*>(Ws + i * 16);
        #pragma unroll
        for (int j = 0; j < 4; j++) {
            float4 w = wr[j];
            acc[4*j+0] = fmaf(hv, w.x, acc[4*j+0]);
            acc[4*j+1] = fmaf(hv, w.y, acc[4*j+1]);
            acc[4*j+2] = fmaf(hv, w.z, acc[4*j+2]);
            acc[4*j+3] = fmaf(hv, w.w, acc[4*j+3]);
        }
    }
    #pragma unroll
    for (int j = 0; j < 16; j++) outr[j] = acc[j];
}

__device__ __forceinline__ void layernorm16(float* __restrict__ v,
                                            const float* __restrict__ g,
                                            const float* __restrict__ b)
{
    float mu = 0.f;
    #pragma unroll
    for (int j = 0; j < 16; j++) mu += v[j];
    mu *= (1.0f / 16.0f);
    float var = 0.f;
    #pragma unroll
    for (int j = 0; j < 16; j++) { float d = v[j] - mu; var = fmaf(d, d, var); }
    var *= (1.0f / 16.0f);
    float r = rsqrtf(var + 1e-5f);
    #pragma unroll
    for (int j = 0; j < 16; j++) v[j] = fmaf((v[j] - mu) * r, g[j], b[j]);
}

// ---------------------------------------------------------------------------
// Kernel 2: fused attention + up-proj + LN + FF(3 linears) + LN + out-proj.
// Grid: (S/128, B).  128 threads, one token each.
// ---------------------------------------------------------------------------
__global__ void __launch_bounds__(128)
attn_fused_kernel(const float* __restrict__ x,
                  const float* __restrict__ Wu, const float* __restrict__ bu,
                  const float* __restrict__ ln_g, const float* __restrict__ ln_b,
                  const float* __restrict__ W1, const float* __restrict__ b1,
                  const float* __restrict__ W2, const float* __restrict__ b2,
                  const float* __restrict__ W3, const float* __restrict__ b3,
                  const float* __restrict__ Wo, const float* __restrict__ bo,
                  float* __restrict__ out)
{
    __shared__ float4 skv[SS];                                // 16 KB
    __shared__ __align__(16) float sW1[256], sW2[256], sW3[256], sWo[256];
    __shared__ __align__(16) float sWu[32];
    __shared__ float sbu[16], sg[16], sb[16], sb1[16], sb2[16], sb3[16], sbo[16];

    int tid = threadIdx.x;
    int b   = blockIdx.y;
    int s   = blockIdx.x * 128 + tid;

    // Cooperative loads
    const float4* kvsrc = g_kv + b * SS;
    #pragma unroll
    for (int i = 0; i < 8; i++) skv[tid + i * 128] = kvsrc[tid + i * 128];

    for (int i = tid; i < 256; i += 128) {
        sW1[i] = W1[i]; sW2[i] = W2[i]; sW3[i] = W3[i]; sWo[i] = Wo[i];
    }
    if (tid < 32) sWu[tid] = Wu[tid];
    if (tid < 16) {
        sbu[tid] = bu[tid]; sg[tid] = ln_g[tid]; sb[tid] = ln_b[tid];
        sb1[tid] = b1[tid]; sb2[tid] = b2[tid];  sb3[tid] = b3[tid];
        sbo[tid] = bo[tid];
    }
    __syncthreads();

    // ---- attention over t (softmax without shift: |score| <= ~3.5) ----
    float2 q = g_q[b * SS + s];
    float l = 0.f, a0 = 0.f, a1 = 0.f;
    #pragma unroll 8
    for (int t = 0; t < SS; t++) {
        float4 kv = skv[t];
        float d = fmaf(q.y, kv.y, q.x * kv.x);   // already in log2 domain
        float p = ex2_approx(d);
        l  += p;
        a0 = fmaf(p, kv.z, a0);
        a1 = fmaf(p, kv.w, a1);
    }
    float inv = 1.0f / l;
    float c0 = a0 * inv, c1 = a1 * inv;

    // ---- ctx @ Wu + bu + residual x ----
    float h[16];
    const float4* xp = reinterpret_cast<const float4*>(x + (b * SS + s) * DD);
    float xr[16];
    #pragma unroll
    for (int c = 0; c < 4; c++) {
        float4 v = xp[c];
        xr[4*c+0] = v.x; xr[4*c+1] = v.y; xr[4*c+2] = v.z; xr[4*c+3] = v.w;
    }
    #pragma unroll
    for (int j = 0; j < 16; j++)
        h[j] = fmaf(c0, sWu[j], fmaf(c1, sWu[16 + j], sbu[j])) + xr[j];

    layernorm16(h, sg, sb);

    // ---- feed-forward: 3 chained 16x16 linears (no nonlinearity) ----
    float t1[16], t2[16], t3[16];
    mm16(h,  sW1, sb1, t1);
    mm16(t1, sW2, sb2, t2);
    mm16(t2, sW3, sb3, t3);
    #pragma unroll
    for (int j = 0; j < 16; j++) t3[j] += h[j];

    layernorm16(t3, sg, sb);

    // ---- output projection ----
    float o[16];
    mm16(t3, sWo, sbo, o);

    float4* op = reinterpret_cast<float4*>(out + (b * SS + s) * DD);
    #pragma unroll
    for (int c = 0; c < 4; c++)
        op[c] = make_float4(o[4*c+0], o[4*c+1], o[4*c+2], o[4*c+3]);
}

// ---------------------------------------------------------------------------
extern "C" void kernel_launch(void* const* d_in, const int* in_sizes, int n_in,
                              void* d_out, int out_size)
{
    const float* x    = (const float*)d_in[0];
    const float* Wq   = (const float*)d_in[1];
    const float* bq   = (const float*)d_in[2];
    const float* Wk   = (const float*)d_in[3];
    const float* bk   = (const float*)d_in[4];
    const float* Wv   = (const float*)d_in[5];
    const float* bv   = (const float*)d_in[6];
    const float* Wu   = (const float*)d_in[7];
    const float* bu   = (const float*)d_in[8];
    const float* ln_g = (const float*)d_in[9];
    const float* ln_b = (const float*)d_in[10];
    const float* W1   = (const float*)d_in[11];
    const float* b1   = (const float*)d_in[12];
    const float* W2   = (const float*)d_in[13];
    const float* b2   = (const float*)d_in[14];
    const float* W3   = (const float*)d_in[15];
    const float* b3   = (const float*)d_in[16];
    const float* Wo   = (const float*)d_in[17];
    const float* bo   = (const float*)d_in[18];
    float* out = (float*)d_out;

    qkv_kernel<<<(BB * SS) / 256, 256>>>(x, Wq, bq, Wk, bk, Wv, bv);

    dim3 grid(SS / 128, BB);
    attn_fused_kernel<<<grid, 128>>>(x, Wu, bu, ln_g, ln_b,
                                     W1, b1, W2, b2, W3, b3, Wo, bo, out);
}